// round 17
// baseline (speedup 1.0000x reference)
#include <cuda_runtime.h>

#define N_NODESC 50000
#define N_EDGESC 800000
#define E2C (N_EDGESC + N_NODESC)
#define D_INC 128
#define D_HIDC 64
#define D_OUTC 32
#define SCAN_BLK 256
#define SCAN_GRID ((N_NODESC + SCAN_BLK - 1) / SCAN_BLK)   // 196

// ---------------- scratch (device globals; never referenced from host) --------
// Zero-initialized at module load. Per-call invariant restore: scatter re-zeros
// count/attr_sum (hidden on side stream), gat layer-0 re-zeros cursor.
__device__ __align__(16) int   g_count[N_NODESC];
__device__ __align__(16) float g_attr_sum[N_NODESC];
__device__ __align__(16) float g_loop_attr[N_NODESC];
__device__ __align__(16) int   g_row_ptr[N_NODESC + 1];
__device__ __align__(16) int   g_cursor[N_NODESC];
__device__ __align__(16) int2  g_csr[E2C];                 // (src, attr-bits)
__device__ __align__(16) int   g_bsum[SCAN_GRID];
__device__ __align__(16) float g_xl [N_NODESC * D_HIDC];
__device__ __align__(16) float g_xr [N_NODESC * D_HIDC];
__device__ __align__(16) float g_h  [N_NODESC * D_HIDC];
__device__ __align__(16) float g_xl2[N_NODESC * D_OUTC];
__device__ __align__(16) float g_xr2[N_NODESC * D_OUTC];

__device__ __forceinline__ const float* lin_in_ptr(const float* xparam, int sel) {
    return (sel == 0) ? xparam : g_h;
}

// ---------------- preprocessing (multi-block; scan2 merged into scan3) ----------
__global__ void count_kernel(const int* __restrict__ ei,
                             const float* __restrict__ ew) {
    int e = blockIdx.x * blockDim.x + threadIdx.x;
    if (e < N_EDGESC) {
        int d = ei[N_EDGESC + e];
        if ((unsigned)d < (unsigned)N_NODESC) {
            atomicAdd(&g_count[d], 1);
            atomicAdd(&g_attr_sum[d], ew[e]);
        }
    }
}

__global__ void scan1_kernel() {   // per-block sums + loop_attr
    __shared__ int red[SCAN_BLK];
    int t = threadIdx.x, b = blockIdx.x;
    int i = b * SCAN_BLK + t;
    int val = 0;
    if (i < N_NODESC) {
        int c = g_count[i];
        val = c + 1;
        g_loop_attr[i] = g_attr_sum[i] / fmaxf((float)c, 1.0f);
    }
    red[t] = val;
    __syncthreads();
#pragma unroll
    for (int off = SCAN_BLK / 2; off > 0; off >>= 1) {
        if (t < off) red[t] += red[t + off];
        __syncthreads();
    }
    if (t == 0) g_bsum[b] = red[0];
}

// local scan + (redundant in-block scan of the 196 block sums) -> row_ptr
__global__ void scan3_kernel() {
    __shared__ int sh[SCAN_BLK];
    __shared__ int pref[SCAN_BLK];
    int t = threadIdx.x, b = blockIdx.x;
    int bs = (t < SCAN_GRID) ? g_bsum[t] : 0;
    pref[t] = bs;
    __syncthreads();
    for (int off = 1; off < SCAN_BLK; off <<= 1) {
        int v = (t >= off) ? pref[t - off] : 0;
        __syncthreads();
        pref[t] += v;
        __syncthreads();
    }
    int boff = (b == 0) ? 0 : pref[b - 1];
    int i = b * SCAN_BLK + t;
    int val = (i < N_NODESC) ? (g_count[i] + 1) : 0;
    sh[t] = val;
    __syncthreads();
    for (int off = 1; off < SCAN_BLK; off <<= 1) {
        int v = (t >= off) ? sh[t - off] : 0;
        __syncthreads();
        sh[t] += v;
        __syncthreads();
    }
    if (i < N_NODESC) g_row_ptr[i] = boff + sh[t] - val;
    if (i == N_NODESC) g_row_ptr[N_NODESC] = E2C;
}

__global__ void scatter_kernel(const int* __restrict__ ei,
                               const float* __restrict__ ew) {
    int e = blockIdx.x * blockDim.x + threadIdx.x;
    // restore zero-invariant for count/attr_sum here (hidden on side stream);
    // safe: scan1 already consumed them, nothing reads them again this call.
    if (e < N_NODESC) {
        g_count[e] = 0;
        g_attr_sum[e] = 0.f;
    }
    if (e < N_EDGESC) {
        int d = ei[N_EDGESC + e];
        int s = ei[e];
        if ((unsigned)d < (unsigned)N_NODESC && (unsigned)s < (unsigned)N_NODESC) {
            int pos = g_row_ptr[d] + atomicAdd(&g_cursor[d], 1);
            g_csr[pos] = make_int2(s, __float_as_int(ew[e]));
        }
    } else if (e < E2C) {
        int v = e - N_EDGESC;
        int pos = g_row_ptr[v] + atomicAdd(&g_cursor[v], 1);
        g_csr[pos] = make_int2(v, __float_as_int(g_loop_attr[v]));
    }
}

// ---------------- fused linear: yl = x@Wl^T+bl, yr = x@Wr^T+br ------------------
// XS = TN+4 (mult of 4): x read is one aligned LDS.128 (3 LDS feed 32 FMA).
// Fill-side 4-way store conflicts are amortized (8 st/thread vs 1200-cyc loop).
template <int DI, int DO, int TN, int KC, int PAIR>
__global__ void __launch_bounds__(256) linear_fused_kernel(
    const float* __restrict__ xparam,
    const float* __restrict__ Wl, const float* __restrict__ bl,
    const float* __restrict__ Wr, const float* __restrict__ br,
    int insel) {
    constexpr int WS   = DO + 4;
    constexpr int XS   = TN + 4;
    constexpr int NT_H = DO / 4;
    constexpr int NT_N = 256 / NT_H;
    constexpr int R_N  = TN / NT_N;
    static_assert(DI % KC == 0 && R_N == 4 && XS % 4 == 0, "tile config");
    __shared__ __align__(16) float Wls[KC * WS];
    __shared__ __align__(16) float Wrs[KC * WS];
    __shared__ __align__(16) float xs[KC * XS];
    const float* __restrict__ x = lin_in_ptr(xparam, insel);
    float* __restrict__ yl = PAIR ? g_xl2 : g_xl;
    float* __restrict__ yr = PAIR ? g_xr2 : g_xr;
    int t = threadIdx.x;
    int node0 = blockIdx.x * TN;
    int h0 = (t % NT_H) * 4;
    int n0 = (t / NT_H) * R_N;      // multiple of 4 -> float4-aligned xs reads
    float accl[R_N][4], accr[R_N][4];
#pragma unroll
    for (int r = 0; r < R_N; r++)
#pragma unroll
        for (int c = 0; c < 4; c++) { accl[r][c] = 0.f; accr[r][c] = 0.f; }

    for (int c = 0; c < DI / KC; c++) {
        if (c) __syncthreads();
        for (int i = t; i < DO * KC; i += 256) {
            int r = i / KC, k = i % KC;
            Wls[k * WS + r] = Wl[r * DI + c * KC + k];
            Wrs[k * WS + r] = Wr[r * DI + c * KC + k];
        }
        for (int i = t; i < TN * KC; i += 256) {
            int n = i / KC, k = i % KC;
            int nd = node0 + n;
            xs[k * XS + n] = (nd < N_NODESC) ? x[nd * DI + c * KC + k] : 0.f;
        }
        __syncthreads();
#pragma unroll 4
        for (int k = 0; k < KC; k++) {
            float4 wl4 = *reinterpret_cast<const float4*>(&Wls[k * WS + h0]);
            float4 wr4 = *reinterpret_cast<const float4*>(&Wrs[k * WS + h0]);
            float4 xv4 = *reinterpret_cast<const float4*>(&xs[k * XS + n0]);
            float xvr[4] = {xv4.x, xv4.y, xv4.z, xv4.w};
#pragma unroll
            for (int r = 0; r < R_N; r++) {
                accl[r][0] = fmaf(xvr[r], wl4.x, accl[r][0]);
                accl[r][1] = fmaf(xvr[r], wl4.y, accl[r][1]);
                accl[r][2] = fmaf(xvr[r], wl4.z, accl[r][2]);
                accl[r][3] = fmaf(xvr[r], wl4.w, accl[r][3]);
                accr[r][0] = fmaf(xvr[r], wr4.x, accr[r][0]);
                accr[r][1] = fmaf(xvr[r], wr4.y, accr[r][1]);
                accr[r][2] = fmaf(xvr[r], wr4.z, accr[r][2]);
                accr[r][3] = fmaf(xvr[r], wr4.w, accr[r][3]);
            }
        }
    }
#pragma unroll
    for (int r = 0; r < R_N; r++) {
        int node = node0 + n0 + r;
        if (node < N_NODESC) {
            float4 o;
            o.x = accl[r][0] + bl[h0 + 0];
            o.y = accl[r][1] + bl[h0 + 1];
            o.z = accl[r][2] + bl[h0 + 2];
            o.w = accl[r][3] + bl[h0 + 3];
            *reinterpret_cast<float4*>(&yl[node * DO + h0]) = o;
            o.x = accr[r][0] + br[h0 + 0];
            o.y = accr[r][1] + br[h0 + 1];
            o.z = accr[r][2] + br[h0 + 2];
            o.w = accr[r][3] + br[h0 + 3];
            *reinterpret_cast<float4*>(&yr[node * DO + h0]) = o;
        }
    }
}

// ---------------- GATv2 node kernel: warp per node, EPI-edge ILP ----------------
// EPI edges per iteration (measured trend R13/R15); tail handled singly.
// LAYER 0 re-zeros g_cursor (count/attr_sum reset moved to scatter).
template <int DH, int EPI, int LAYER>
__global__ void __launch_bounds__(256) gat_node_kernel(
    const float* __restrict__ We, const float* __restrict__ att,
    const float* __restrict__ bias, float* __restrict__ outp) {
    constexpr int PER = DH / 32;
    const float* __restrict__ xl = (LAYER == 0) ? g_xl : g_xl2;
    const float* __restrict__ xr = (LAYER == 0) ? g_xr : g_xr2;
    float* __restrict__ out = (LAYER == 0) ? g_h : outp;
    int gi = blockIdx.x * blockDim.x + threadIdx.x;
    if (LAYER == 0 && gi < N_NODESC) g_cursor[gi] = 0;   // zero-invariant
    int v    = gi >> 5;
    int lane = gi & 31;
    if (v >= N_NODESC) return;

    float xrv[PER], wev[PER], attv[PER], bv[PER];
#pragma unroll
    for (int p = 0; p < PER; p++) {
        int h = lane * PER + p;
        xrv[p]  = xr[v * DH + h];
        wev[p]  = We[h];
        attv[p] = att[h];
        bv[p]   = bias[h];
    }
    int beg = g_row_ptr[v], end = g_row_ptr[v + 1];   // end > beg (self loop)

    float ssum = 0.f;
    float acc[PER];
#pragma unroll
    for (int p = 0; p < PER; p++) acc[p] = 0.f;

    int idx = beg;
    for (; idx + EPI - 1 < end; idx += EPI) {
        int2 e[EPI];
        float xv[EPI][PER], a[EPI], sc[EPI];
#pragma unroll
        for (int j = 0; j < EPI; j++) e[j] = g_csr[idx + j];
#pragma unroll
        for (int j = 0; j < EPI; j++) {
            const float* pj = xl + (size_t)e[j].x * DH + lane * PER;
            if (PER == 2) {
                float2 t2 = *reinterpret_cast<const float2*>(pj);
                xv[j][0] = t2.x; xv[j][1] = t2.y;
            } else {
                xv[j][0] = *pj;
            }
            a[j] = __int_as_float(e[j].y);
            sc[j] = 0.f;
        }
#pragma unroll
        for (int j = 0; j < EPI; j++) {
#pragma unroll
            for (int p = 0; p < PER; p++) {
                float m = xv[j][p] + xrv[p] + a[j] * wev[p];
                m = m > 0.f ? m : 0.2f * m;
                sc[j] = fmaf(attv[p], m, sc[j]);
            }
        }
#pragma unroll
        for (int o = 16; o; o >>= 1) {
#pragma unroll
            for (int j = 0; j < EPI; j++)
                sc[j] += __shfl_xor_sync(0xffffffffu, sc[j], o);
        }
#pragma unroll
        for (int j = 0; j < EPI; j++) {
            float ex = __expf(sc[j]);
            ssum += ex;
#pragma unroll
            for (int p = 0; p < PER; p++) acc[p] = fmaf(ex, xv[j][p], acc[p]);
        }
    }
    for (; idx < end; idx++) {            // tail
        int2 e0 = g_csr[idx];
        const float* p0 = xl + (size_t)e0.x * DH + lane * PER;
        float x0[PER];
        if (PER == 2) {
            float2 t0 = *reinterpret_cast<const float2*>(p0);
            x0[0] = t0.x; x0[1] = t0.y;
        } else {
            x0[0] = *p0;
        }
        float a0 = __int_as_float(e0.y);
        float sc0 = 0.f;
#pragma unroll
        for (int p = 0; p < PER; p++) {
            float m0 = x0[p] + xrv[p] + a0 * wev[p];
            m0 = m0 > 0.f ? m0 : 0.2f * m0;
            sc0 = fmaf(attv[p], m0, sc0);
        }
#pragma unroll
        for (int o = 16; o; o >>= 1) sc0 += __shfl_xor_sync(0xffffffffu, sc0, o);
        float ex0 = __expf(sc0);
        ssum += ex0;
#pragma unroll
        for (int p = 0; p < PER; p++) acc[p] = fmaf(ex0, x0[p], acc[p]);
    }

    float inv = 1.f / ssum;
#pragma unroll
    for (int p = 0; p < PER; p++) {
        float o = fmaf(acc[p], inv, bv[p]);
        if (LAYER == 0) {
            o = o > 0.f ? o : (__expf(o) - 1.f);            // elu
        } else {
            o = (o > 20.f ? o : log1pf(__expf(o))) + 1e-4f; // softplus + eps
        }
        out[v * DH + lane * PER + p] = o;
    }
}

// ---------------- launch --------------------------------------------------------
// Two-stream fork/join inside graph capture (R16-proven): CSR chain on a side
// stream concurrently with linear1; join before gat1.
extern "C" void kernel_launch(void* const* d_in, const int* in_sizes, int n_in,
                              void* d_out, int out_size) {
    const float* x     = (const float*)d_in[0];
    const int*   ei    = (const int*)d_in[1];      // edge_index: int32
    const float* ew    = (const float*)d_in[2];
    const float* Wl1   = (const float*)d_in[3];
    const float* bl1   = (const float*)d_in[4];
    const float* Wr1   = (const float*)d_in[5];
    const float* br1   = (const float*)d_in[6];
    const float* We1   = (const float*)d_in[7];
    const float* att1  = (const float*)d_in[8];
    const float* bias1 = (const float*)d_in[9];
    const float* Wl2   = (const float*)d_in[10];
    const float* bl2   = (const float*)d_in[11];
    const float* Wr2   = (const float*)d_in[12];
    const float* br2   = (const float*)d_in[13];
    const float* We2   = (const float*)d_in[14];
    const float* att2  = (const float*)d_in[15];
    const float* bias2 = (const float*)d_in[16];
    float*       out   = (float*)d_out;

    cudaStream_t s2;
    cudaStreamCreateWithFlags(&s2, cudaStreamNonBlocking);
    cudaEvent_t evFork, evJoin;
    cudaEventCreateWithFlags(&evFork, cudaEventDisableTiming);
    cudaEventCreateWithFlags(&evJoin, cudaEventDisableTiming);

    const int GRID_GAT = (N_NODESC * 32 + 255) / 256;   // warp per node

    // fork: side stream joins the capture graph via event dependency
    cudaEventRecord(evFork, 0);
    cudaStreamWaitEvent(s2, evFork, 0);

    // ---- CSR chain on side stream (independent of linear1) ----
    count_kernel<<<(N_EDGESC + 255) / 256, 256, 0, s2>>>(ei, ew);
    scan1_kernel<<<SCAN_GRID, SCAN_BLK, 0, s2>>>();
    scan3_kernel<<<SCAN_GRID, SCAN_BLK, 0, s2>>>();
    scatter_kernel<<<(E2C + 255) / 256, 256, 0, s2>>>(ei, ew);
    cudaEventRecord(evJoin, s2);

    // ---- linear1 on main stream, concurrent with the CSR chain ----
    linear_fused_kernel<D_INC, D_HIDC, 64, 32, 0><<<(N_NODESC + 63) / 64, 256>>>(
        x, Wl1, bl1, Wr1, br1, 0);

    // join: gat1 needs both linear1 (main) and scatter (side)
    cudaStreamWaitEvent(0, evJoin, 0);
    gat_node_kernel<D_HIDC, 6, 0><<<GRID_GAT, 256>>>(We1, att1, bias1, out);

    // ---- layer 2 (serial dependencies) ----
    linear_fused_kernel<D_HIDC, D_OUTC, 128, 32, 1><<<(N_NODESC + 127) / 128, 256>>>(
        x, Wl2, bl2, Wr2, br2, 1);
    gat_node_kernel<D_OUTC, 8, 1><<<GRID_GAT, 256>>>(We2, att2, bias2, out);
}